// round 13
// baseline (speedup 1.0000x reference)
#include <cuda_runtime.h>
#include <cuda_bf16.h>
#include <cuda_fp16.h>
#include <math.h>
#include <stdint.h>

// Model dims
#define LNUM 12
#define DMODEL 768
#define NHEAD 6
#define HDIM 128
#define FFDIM 3072
#define VOCAB 65536
#define SEQ 2048
#define EPSV 1e-5f
#define CAPV 30.0f

#define K3D (3 * DMODEL)    // 2304
#define K2D (2 * DMODEL)    // 1536 (lm_head 2-plane K)
#define K3F (3 * FFDIM)     // 9216

// GEMM tiling: 128x128 tile, BK=64, 3-stage cp.async, 2 CTAs/SM
#define LDS 72
#define SMEM_BYTES (3 * 128 * LDS * 2 * 2)           // 110592 B
// 64x128 variant: A 64 rows + B 128 rows per stage
#define SMEM64_BYTES (3 * (64 + 128) * LDS * 2)      // 82944 B

// ---------------- scratch (static device arrays; no allocation) -------------
__device__ float g_x[SEQ * DMODEL];
__device__ float g_big[SEQ * K3D];
__device__ float g_q[SEQ * DMODEL];
__device__ float g_k[SEQ * DMODEL];
__device__ float g_v[SEQ * DMODEL];
__device__ float g_rowsum[SEQ];
__device__ float g_tl[SEQ];

// K-interleaved fp16 split planes: row n, cols [0,K)=hi,[K,2K)=lo,[2K,3K)=hi
__device__ __align__(16) __half w3_qkv[12LL * 2304 * K3D];
__device__ __align__(16) __half w3_proj[12LL * 768 * K3D];
__device__ __align__(16) __half w3_fc1[12LL * 3072 * K3D];
__device__ __align__(16) __half w3_fc2[12LL * 768 * K3F];
// lm_head: 2-plane [hi|lo], row stride K2D
__device__ __align__(16) __half w2_lm[65536LL * K2D];

// K-interleaved activation planes: row t, cols [0,K)=hi,[K,2K)=hi,[2K,3K)=lo
__device__ __align__(16) __half an3[SEQ * K3D];
__device__ __align__(16) __half ah3[SEQ * K3F];

// ---------------- helpers ----------------------------------------------------
__device__ __forceinline__ void split2h(float v, __half& h, __half& l) {
    h = __float2half_rn(v);
    l = __float2half_rn(v - __half2float(h));
}

__device__ __forceinline__ float blockReduceSum(float v) {
    __shared__ float sh[32];
    __syncthreads();
    int lane = threadIdx.x & 31, wid = threadIdx.x >> 5;
    #pragma unroll
    for (int o = 16; o; o >>= 1) v += __shfl_xor_sync(0xffffffffu, v, o);
    if (lane == 0) sh[wid] = v;
    __syncthreads();
    int nw = blockDim.x >> 5;
    v = (threadIdx.x < nw) ? sh[threadIdx.x] : 0.f;
    if (wid == 0) {
        #pragma unroll
        for (int o = 16; o; o >>= 1) v += __shfl_xor_sync(0xffffffffu, v, o);
        if (lane == 0) sh[0] = v;
    }
    __syncthreads();
    return sh[0];
}

__device__ __forceinline__ void ldsm4(uint32_t (&r)[4], uint32_t addr) {
    asm volatile("ldmatrix.sync.aligned.m8n8.x4.shared.b16 {%0,%1,%2,%3},[%4];"
                 : "=r"(r[0]), "=r"(r[1]), "=r"(r[2]), "=r"(r[3]) : "r"(addr));
}

__device__ __forceinline__ void mma_f32acc(float (&d)[4], const uint32_t (&a)[4],
                                           uint32_t b0, uint32_t b1) {
    asm volatile(
        "mma.sync.aligned.m16n8k16.row.col.f32.f16.f16.f32 "
        "{%0,%1,%2,%3},{%4,%5,%6,%7},{%8,%9},{%0,%1,%2,%3};"
        : "+f"(d[0]), "+f"(d[1]), "+f"(d[2]), "+f"(d[3])
        : "r"(a[0]), "r"(a[1]), "r"(a[2]), "r"(a[3]), "r"(b0), "r"(b1));
}

__device__ __forceinline__ void cp16(uint32_t dst, const void* src) {
    asm volatile("cp.async.cg.shared.global [%0], [%1], 16;" :: "r"(dst), "l"(src));
}
#define CP_COMMIT() asm volatile("cp.async.commit_group;")
#define CP_WAIT1() asm volatile("cp.async.wait_group 1;")

// load one 128x64 fp16 tile of A and B into a stage; separate row strides
__device__ __forceinline__ void load_stage(uint32_t sA, uint32_t sB,
                                           const __half* gA, const __half* gB,
                                           int ldA, int ldB, int tid) {
    int tRow = tid >> 3, tc = (tid & 7) * 8;
    #pragma unroll
    for (int p = 0; p < 4; p++) {
        int row = tRow + 32 * p;
        cp16(sA + (uint32_t)(row * LDS + tc) * 2, gA + (size_t)row * ldA + tc);
        cp16(sB + (uint32_t)(row * LDS + tc) * 2, gB + (size_t)row * ldB + tc);
    }
}

// load A[64x64] + B[128x64] (6 cp16/thread)
__device__ __forceinline__ void load_stage64(uint32_t sA, uint32_t sB,
                                             const __half* gA, const __half* gB,
                                             int Kp, int tid) {
    int ar = tid >> 2, ac = (tid & 3) * 16;     // 64 rows, 4 thr/row x 2 chunks
    cp16(sA + (uint32_t)(ar * LDS + ac) * 2, gA + (size_t)ar * Kp + ac);
    cp16(sA + (uint32_t)(ar * LDS + ac + 8) * 2, gA + (size_t)ar * Kp + ac + 8);
    int br = tid >> 1, bc = (tid & 1) * 32;     // 128 rows, 2 thr/row x 4 chunks
    #pragma unroll
    for (int c = 0; c < 4; c++)
        cp16(sB + (uint32_t)(br * LDS + bc + c * 8) * 2,
             gB + (size_t)br * Kp + bc + c * 8);
}

// ---------------- fused weight split: ONE launch -------------------------------
__device__ __forceinline__ void split_seg3(const float4* s, __half* d,
                                           unsigned n4, unsigned K,
                                           unsigned gid, unsigned gstride) {
    unsigned K4 = K >> 2;
    for (unsigned i = gid; i < n4; i += gstride) {
        float4 v = s[i];
        unsigned n = i / K4;
        unsigned k = (i - n * K4) << 2;
        __half* r = d + (size_t)n * 3 * K + k;
        float vv[4] = {v.x, v.y, v.z, v.w};
        #pragma unroll
        for (int j = 0; j < 4; j++) {
            __half h, l;
            split2h(vv[j], h, l);
            r[j] = h; r[K + j] = l; r[2 * K + j] = h;
        }
    }
}

__device__ __forceinline__ void split_seg2(const float4* s, __half* d,
                                           unsigned n4, unsigned K,
                                           unsigned gid, unsigned gstride) {
    unsigned K4 = K >> 2;
    for (unsigned i = gid; i < n4; i += gstride) {
        float4 v = s[i];
        unsigned n = i / K4;
        unsigned k = (i - n * K4) << 2;
        __half* r = d + (size_t)n * 2 * K + k;
        float vv[4] = {v.x, v.y, v.z, v.w};
        #pragma unroll
        for (int j = 0; j < 4; j++) {
            __half h, l;
            split2h(vv[j], h, l);
            r[j] = h; r[K + j] = l;
        }
    }
}

__global__ void split_all_kernel(const float4* qkv, const float4* proj,
                                 const float4* fc1, const float4* fc2,
                                 const float4* lm,
                                 __half* dqkv, __half* dproj,
                                 __half* dfc1, __half* dfc2, __half* dlm) {
    unsigned gid = blockIdx.x * blockDim.x + threadIdx.x;
    unsigned gs = gridDim.x * blockDim.x;
    split_seg3(qkv, dqkv, 12u * 2304 * 768 / 4, DMODEL, gid, gs);
    split_seg3(proj, dproj, 12u * 768 * 768 / 4, DMODEL, gid, gs);
    split_seg3(fc1, dfc1, 12u * 3072 * 768 / 4, DMODEL, gid, gs);
    split_seg3(fc2, dfc2, 12u * 768 * 3072 / 4, FFDIM, gid, gs);
    split_seg2(lm, dlm, 65536u * 768 / 4, DMODEL, gid, gs);
}

// ---------------- elementwise kernels ----------------------------------------
__global__ void embed_kernel(const int* __restrict__ idx,
                             const float* __restrict__ emb) {
    int t = blockIdx.x;
    int row = idx[t];
    const float* src = emb + (size_t)row * DMODEL;
    for (int i = threadIdx.x; i < DMODEL; i += blockDim.x)
        g_x[t * DMODEL + i] = src[i];
}

__global__ void rmsnorm_kernel(const float* __restrict__ x,
                               const float* __restrict__ w) {
    int t = blockIdx.x;
    const float* xr = x + (size_t)t * DMODEL;
    float s = 0.f;
    for (int i = threadIdx.x; i < DMODEL; i += blockDim.x) {
        float v = xr[i];
        s += v * v;
    }
    s = blockReduceSum(s);
    float r = rsqrtf(s / (float)DMODEL + EPSV);
    for (int i = threadIdx.x; i < DMODEL; i += blockDim.x) {
        float v = xr[i] * r * w[i];
        __half h, l;
        split2h(v, h, l);
        size_t o = (size_t)t * K3D + i;
        an3[o] = h; an3[o + DMODEL] = h; an3[o + 2 * DMODEL] = l;
    }
}

__global__ void rope_kernel(const float* __restrict__ qkv,
                            const float* __restrict__ qw,
                            const float* __restrict__ kw) {
    int t = blockIdx.x, h = blockIdx.y, d = threadIdx.x;
    const float* base = qkv + (size_t)t * K3D;
    float qd = base[h * HDIM + d];
    float kd = base[DMODEL + h * HDIM + d];
    float vd = base[2 * DMODEL + h * HDIM + d];
    float qs = blockReduceSum(qd * qd);
    float ks = blockReduceSum(kd * kd);
    float qn = qd * rsqrtf(qs / (float)HDIM + EPSV) * qw[d];
    float kn = kd * rsqrtf(ks / (float)HDIM + EPSV) * kw[d];
    __shared__ float sq[HDIM], sk[HDIM];
    sq[d] = qn; sk[d] = kn;
    __syncthreads();
    float expo = -(float)((d & 63) * 2) / (float)HDIM;
    float invf = expf(expo * logf(10000.f));
    float ang = (float)t * invf;
    float c = cosf(ang), s = sinf(ang);
    float qr = (d < 64) ? -sq[d + 64] : sq[d - 64];
    float kr = (d < 64) ? -sk[d + 64] : sk[d - 64];
    size_t oidx = (size_t)t * DMODEL + h * HDIM + d;
    g_q[oidx] = qn * c + qr * s;
    g_k[oidx] = kn * c + kr * s;
    g_v[oidx] = vd;
}

// ---------------- attention: tile-wise online softmax (lane = key) -----------
__global__ void __launch_bounds__(256) attn_kernel() {
    const int h = blockIdx.y;
    const int qbase = blockIdx.x * 8;
    const int tid = threadIdx.x;
    const int warp = tid >> 5, lane = tid & 31;
    const int qi = qbase + warp;
    __shared__ float4 Ktf[32][33];
    __shared__ float4 Vtf[32][33];
    __shared__ float4 sq4[8][32];

    {
        int r = tid >> 5, c4 = tid & 31;
        sq4[r][c4] = ((const float4*)(g_q + (size_t)(qbase + r) * DMODEL +
                                      h * HDIM))[c4];
    }

    float m = -1e30f, l = 0.f;
    float4 acc = make_float4(0.f, 0.f, 0.f, 0.f);
    const int ntiles = (qbase + 8 + 31) >> 5;

    for (int tb = 0; tb < ntiles; tb++) {
        int kb = tb << 5;
        __syncthreads();
        #pragma unroll
        for (int it = 0; it < 4; it++) {
            int i = tid + it * 256;
            int r = i >> 5, c4 = i & 31;
            Ktf[c4][r] = ((const float4*)(g_k + (size_t)(kb + r) * DMODEL +
                                          h * HDIM))[c4];
            Vtf[r][c4] = ((const float4*)(g_v + (size_t)(kb + r) * DMODEL +
                                          h * HDIM))[c4];
        }
        __syncthreads();

        int jmax = qi - kb + 1;
        if (jmax > 0) {
            float s0 = 0.f, s1 = 0.f, s2 = 0.f, s3 = 0.f;
            #pragma unroll
            for (int d4 = 0; d4 < 32; d4 += 4) {
                float4 q0 = sq4[warp][d4],     k0 = Ktf[d4][lane];
                float4 q1 = sq4[warp][d4 + 1], k1 = Ktf[d4 + 1][lane];
                float4 q2 = sq4[warp][d4 + 2], k2 = Ktf[d4 + 2][lane];
                float4 q3 = sq4[warp][d4 + 3], k3 = Ktf[d4 + 3][lane];
                s0 += q0.x * k0.x + q0.y * k0.y + q0.z * k0.z + q0.w * k0.w;
                s1 += q1.x * k1.x + q1.y * k1.y + q1.z * k1.z + q1.w * k1.w;
                s2 += q2.x * k2.x + q2.y * k2.y + q2.z * k2.z + q2.w * k2.w;
                s3 += q3.x * k3.x + q3.y * k3.y + q3.z * k3.z + q3.w * k3.w;
            }
            float sv = (s0 + s1 + s2 + s3) * 0.08838834764831845f;
            if (lane >= jmax) sv = -1e30f;
            float mt = sv;
            #pragma unroll
            for (int o = 16; o; o >>= 1)
                mt = fmaxf(mt, __shfl_xor_sync(0xffffffffu, mt, o));
            float mn = fmaxf(m, mt);
            float corr = __expf(m - mn);
            float p = __expf(sv - mn);
            float psum = p;
            #pragma unroll
            for (int o = 16; o; o >>= 1)
                psum += __shfl_xor_sync(0xffffffffu, psum, o);
            l = l * corr + psum;
            m = mn;
            acc.x *= corr; acc.y *= corr; acc.z *= corr; acc.w *= corr;
            #pragma unroll
            for (int j = 0; j < 32; j++) {
                float pj = __shfl_sync(0xffffffffu, p, j);
                float4 vv = Vtf[j][lane];
                acc.x += pj * vv.x; acc.y += pj * vv.y;
                acc.z += pj * vv.z; acc.w += pj * vv.w;
            }
        }
    }
    float inv = 1.f / l;
    float ov[4] = {acc.x * inv, acc.y * inv, acc.z * inv, acc.w * inv};
    #pragma unroll
    for (int q = 0; q < 4; q++) {
        int i = h * HDIM + lane * 4 + q;
        __half hh, ll;
        split2h(ov[q], hh, ll);
        size_t o = (size_t)qi * K3D + i;
        an3[o] = hh; an3[o + DMODEL] = hh; an3[o + 2 * DMODEL] = ll;
    }
}

// ---------------- pipelined fp16 GEMM 128x128: C = A * B^T --------------------
__global__ void __launch_bounds__(256, 2)
gemm_kernel(const __half* __restrict__ A, const __half* __restrict__ B,
            float* __restrict__ C, const float* __restrict__ res,
            __half* __restrict__ O3,
            int M, int N, int Kp, int epi) {
    extern __shared__ __half smem[];
    __half* sA = smem;
    __half* sB = smem + 3 * 128 * LDS;
    const int tid = threadIdx.x, lane = tid & 31, wid = tid >> 5;
    const int wm = wid >> 2, wn = wid & 3;
    const int m0 = blockIdx.x * 128, n0 = blockIdx.y * 128;
    const uint32_t sAu = (uint32_t)__cvta_generic_to_shared(sA);
    const uint32_t sBu = (uint32_t)__cvta_generic_to_shared(sB);
    const uint32_t stageB = 128 * LDS * 2;
    const __half* gA = A + (size_t)m0 * Kp;
    const __half* gB = B + (size_t)n0 * Kp;

    float acc[4][4][4];
    #pragma unroll
    for (int a = 0; a < 4; a++)
        #pragma unroll
        for (int b = 0; b < 4; b++)
            #pragma unroll
            for (int c = 0; c < 4; c++) acc[a][b][c] = 0.f;

    const int nk = Kp / 64;
    load_stage(sAu, sBu, gA, gB, Kp, Kp, tid);
    CP_COMMIT();
    load_stage(sAu + stageB, sBu + stageB, gA + 64, gB + 64, Kp, Kp, tid);
    CP_COMMIT();

    for (int k = 0; k < nk; k++) {
        CP_WAIT1();
        __syncthreads();
        int st = k % 3;
        uint32_t aB = sAu + st * stageB;
        uint32_t bB = sBu + st * stageB;
        #pragma unroll
        for (int kh = 0; kh < 4; kh++) {
            uint32_t a[4][4], b[2][4];
            const int acol = kh * 16 + ((lane >> 4) << 3);
            #pragma unroll
            for (int mt = 0; mt < 4; mt++) {
                int arow = wm * 64 + mt * 16 + (lane & 15);
                ldsm4(a[mt], aB + (uint32_t)(arow * LDS + acol) * 2);
            }
            const int brow = wn * 32 + ((lane >> 4) << 3) + (lane & 7);
            const int bcol = kh * 16 + (((lane >> 3) & 1) << 3);
            #pragma unroll
            for (int p = 0; p < 2; p++)
                ldsm4(b[p], bB + (uint32_t)((brow + p * 16) * LDS + bcol) * 2);
            #pragma unroll
            for (int mt = 0; mt < 4; mt++)
                #pragma unroll
                for (int nt = 0; nt < 4; nt++)
                    mma_f32acc(acc[mt][nt], a[mt], b[nt >> 1][(nt & 1) * 2],
                               b[nt >> 1][(nt & 1) * 2 + 1]);
        }
        if (k + 2 < nk) {
            int s2 = (k + 2) % 3;
            load_stage(sAu + s2 * stageB, sBu + s2 * stageB,
                       gA + (size_t)(k + 2) * 64, gB + (size_t)(k + 2) * 64,
                       Kp, Kp, tid);
        }
        CP_COMMIT();
    }
    #pragma unroll
    for (int mt = 0; mt < 4; mt++)
        #pragma unroll
        for (int nt = 0; nt < 4; nt++)
            #pragma unroll
            for (int r = 0; r < 4; r++) {
                int row = m0 + wm * 64 + mt * 16 + (lane >> 2) + (r >> 1) * 8;
                int col = n0 + wn * 32 + nt * 8 + (lane & 3) * 2 + (r & 1);
                float vv = acc[mt][nt][r];
                if (epi == 0) {
                    C[(size_t)row * N + col] = vv;
                } else if (epi == 1) {
                    size_t o = (size_t)row * N + col;
                    C[o] = vv + res[o];
                } else {
                    vv = fmaxf(vv, 0.f); vv = vv * vv;
                    __half h, l;
                    split2h(vv, h, l);
                    size_t o = (size_t)row * 3 * N + col;
                    O3[o] = h; O3[o + N] = h; O3[o + 2 * N] = l;
                }
            }
}

// ---------------- fp16 GEMM 64x128 (narrow-N: proj/fc2, epi=1) ----------------
// 8 warps as 2(M) x 4(N); per-warp 32x32. Same K-order as 128-tile kernel.
__global__ void __launch_bounds__(256, 2)
gemm64_kernel(const __half* __restrict__ A, const __half* __restrict__ B,
              float* __restrict__ C, const float* __restrict__ res,
              int N, int Kp) {
    extern __shared__ __half smem[];
    __half* sA = smem;                       // 3 stages x 64 rows
    __half* sB = smem + 3 * 64 * LDS;        // 3 stages x 128 rows
    const int tid = threadIdx.x, lane = tid & 31, wid = tid >> 5;
    const int wm = wid >> 2, wn = wid & 3;   // 2 x 4
    const int m0 = blockIdx.x * 64, n0 = blockIdx.y * 128;
    const uint32_t sAu = (uint32_t)__cvta_generic_to_shared(sA);
    const uint32_t sBu = (uint32_t)__cvta_generic_to_shared(sB);
    const uint32_t stA = 64 * LDS * 2, stB = 128 * LDS * 2;
    const __half* gA = A + (size_t)m0 * Kp;
    const __half* gB = B + (size_t)n0 * Kp;

    float acc[2][4][4];
    #pragma unroll
    for (int a = 0; a < 2; a++)
        #pragma unroll
        for (int b = 0; b < 4; b++)
            #pragma unroll
            for (int c = 0; c < 4; c++) acc[a][b][c] = 0.f;

    const int nk = Kp / 64;
    load_stage64(sAu, sBu, gA, gB, Kp, tid);
    CP_COMMIT();
    load_stage64(sAu + stA, sBu + stB, gA + 64, gB + 64, Kp, tid);
    CP_COMMIT();

    for (int k = 0; k < nk; k++) {
        CP_WAIT1();
        __syncthreads();
        int st = k % 3;
        uint32_t aB = sAu + st * stA;
        uint32_t bB = sBu + st * stB;
        #pragma unroll
        for (int kh = 0; kh < 4; kh++) {
            uint32_t a[2][4], b[2][4];
            const int acol = kh * 16 + ((lane >> 4) << 3);
            #pragma unroll
            for (int mt = 0; mt < 2; mt++) {
                int arow = wm * 32 + mt * 16 + (lane & 15);
                ldsm4(a[mt], aB + (uint32_t)(arow * LDS + acol) * 2);
            }
            const int brow = wn * 32 + ((lane >> 4) << 3) + (lane & 7);
            const int bcol = kh * 16 + (((lane >> 3) & 1) << 3);
            #pragma unroll
            for (int p = 0; p < 2; p++)
                ldsm4(b[p], bB + (uint32_t)((brow + p * 16) * LDS + bcol) * 2);
            #pragma unroll
            for (int mt = 0; mt < 2; mt++)
                #pragma unroll
                for (int nt = 0; nt < 4; nt++)
                    mma_f32acc(acc[mt][nt], a[mt], b[nt >> 1][(nt & 1) * 2],
                               b[nt >> 1][(nt & 1) * 2 + 1]);
        }
        if (k + 2 < nk) {
            int s2 = (k + 2) % 3;
            load_stage64(sAu + s2 * stA, sBu + s2 * stB,
                         gA + (size_t)(k + 2) * 64, gB + (size_t)(k + 2) * 64,
                         Kp, tid);
        }
        CP_COMMIT();
    }
    #pragma unroll
    for (int mt = 0; mt < 2; mt++)
        #pragma unroll
        for (int nt = 0; nt < 4; nt++)
            #pragma unroll
            for (int r = 0; r < 4; r++) {
                int row = m0 + wm * 32 + mt * 16 + (lane >> 2) + (r >> 1) * 8;
                int col = n0 + wn * 32 + nt * 8 + (lane & 3) * 2 + (r & 1);
                size_t o = (size_t)row * N + col;
                C[o] = acc[mt][nt][r] + res[o];
            }
}

// ---------------- lm_head: 2-plane GEMM (A stride K3D, Kp=K2D) ---------------
__global__ void __launch_bounds__(256, 2)
lmhead_kernel(const __half* __restrict__ A, const __half* __restrict__ B,
              float* __restrict__ out, const int* __restrict__ targets, int store) {
    const int N = VOCAB, Kp = K2D, ldA = K3D;
    extern __shared__ __half smem[];
    __half* sA = smem;
    __half* sB = smem + 3 * 128 * LDS;
    const int tid = threadIdx.x, lane = tid & 31, wid = tid >> 5;
    const int wm = wid >> 2, wn = wid & 3;
    const int m0 = blockIdx.x * 128, n0 = blockIdx.y * 128;
    const uint32_t sAu = (uint32_t)__cvta_generic_to_shared(sA);
    const uint32_t sBu = (uint32_t)__cvta_generic_to_shared(sB);
    const uint32_t stageB = 128 * LDS * 2;
    const __half* gA = A + (size_t)m0 * ldA;
    const __half* gB = B + (size_t)n0 * Kp;

    float acc[4][4][4];
    #pragma unroll
    for (int a = 0; a < 4; a++)
        #pragma unroll
        for (int b = 0; b < 4; b++)
            #pragma unroll
            for (int c = 0; c < 4; c++) acc[a][b][c] = 0.f;

    const int nk = Kp / 64;   // 24
    load_stage(sAu, sBu, gA, gB, ldA, Kp, tid);
    CP_COMMIT();
    load_stage(sAu + stageB, sBu + stageB, gA + 64, gB + 64, ldA, Kp, tid);
    CP_COMMIT();

    for (int k = 0; k < nk; k++) {
        CP_WAIT1();
        __syncthreads();
        int st = k % 3;
        uint32_t aB = sAu + st * stageB;
        uint32_t bB = sBu + st * stageB;
        #pragma unroll
        for (int kh = 0; kh < 4; kh++) {
            uint32_t a[4][4], b[2][4];
            const int acol = kh * 16 + ((lane >> 4) << 3);
            #pragma unroll
            for (int mt = 0; mt < 4; mt++) {
                int arow = wm * 64 + mt * 16 + (lane & 15);
                ldsm4(a[mt], aB + (uint32_t)(arow * LDS + acol) * 2);
            }
            const int brow = wn * 32 + ((lane >> 4) << 3) + (lane & 7);
            const int bcol = kh * 16 + (((lane >> 3) & 1) << 3);
            #pragma unroll
            for (int p = 0; p < 2; p++)
                ldsm4(b[p], bB + (uint32_t)((brow + p * 16) * LDS + bcol) * 2);
            #pragma unroll
            for (int mt = 0; mt < 4; mt++)
                #pragma unroll
                for (int nt = 0; nt < 4; nt++)
                    mma_f32acc(acc[mt][nt], a[mt], b[nt >> 1][(nt & 1) * 2],
                               b[nt >> 1][(nt & 1) * 2 + 1]);
        }
        if (k + 2 < nk) {
            int s2 = (k + 2) % 3;
            load_stage(sAu + s2 * stageB, sBu + s2 * stageB,
                       gA + (size_t)(k + 2) * 64, gB + (size_t)(k + 2) * 64,
                       ldA, Kp, tid);
        }
        CP_COMMIT();
    }
    float ps[8];
    #pragma unroll
    for (int i = 0; i < 8; i++) ps[i] = 0.f;
    #pragma unroll
    for (int mt = 0; mt < 4; mt++)
        #pragma unroll
        for (int nt = 0; nt < 4; nt++)
            #pragma unroll
            for (int r = 0; r < 4; r++) {
                int row = m0 + wm * 64 + mt * 16 + (lane >> 2) + (r >> 1) * 8;
                int col = n0 + wn * 32 + nt * 8 + (lane & 3) * 2 + (r & 1);
                float vv = CAPV * tanhf(acc[mt][nt][r] * (1.f / CAPV));
                if (store)
                    out[(size_t)row * N + col] =
                        __bfloat162float(__float2bfloat16(vv));
                ps[mt * 2 + (r >> 1)] += __expf(vv - CAPV);
                if (col == targets[row]) g_tl[row] = vv;
            }
    #pragma unroll
    for (int i = 0; i < 8; i++) {
        ps[i] += __shfl_xor_sync(0xffffffffu, ps[i], 1);
        ps[i] += __shfl_xor_sync(0xffffffffu, ps[i], 2);
    }
    __syncthreads();
    float* red = (float*)smem;
    if ((lane & 3) == 0) {
        #pragma unroll
        for (int mt = 0; mt < 4; mt++)
            #pragma unroll
            for (int hh = 0; hh < 2; hh++) {
                int rl = wm * 64 + mt * 16 + (lane >> 2) + hh * 8;
                red[rl * 4 + wn] = ps[mt * 2 + hh];
            }
    }
    __syncthreads();
    if (tid < 128) {
        float s = red[tid * 4] + red[tid * 4 + 1] + red[tid * 4 + 2] + red[tid * 4 + 3];
        atomicAdd(&g_rowsum[m0 + tid], s);
    }
}

__global__ void zero_kernel() {
    for (int i = threadIdx.x; i < SEQ; i += blockDim.x) g_rowsum[i] = 0.f;
}

__global__ void loss_kernel(float* out_f) {
    float s = 0.f;
    for (int t = threadIdx.x; t < SEQ; t += blockDim.x)
        s += CAPV + logf(g_rowsum[t]) - g_tl[t];
    s = blockReduceSum(s);
    if (threadIdx.x == 0 && out_f) out_f[0] = s / (float)SEQ;
}

// ---------------- launch ------------------------------------------------------
extern "C" void kernel_launch(void* const* d_in, const int* in_sizes, int n_in,
                              void* d_out, int out_size) {
    const int*   idx     = (const int*)d_in[0];
    const int*   targets = (const int*)d_in[1];
    const float* emb     = (const float*)d_in[2];
    const float* ln1_w   = (const float*)d_in[3];
    const float* qkv_w   = (const float*)d_in[4];
    const float* q_norm  = (const float*)d_in[5];
    const float* k_norm  = (const float*)d_in[6];
    const float* proj_w  = (const float*)d_in[7];
    const float* ln2_w   = (const float*)d_in[8];
    const float* fc1_w   = (const float*)d_in[9];
    const float* fc2_w   = (const float*)d_in[10];
    const float* lnf_w   = (const float*)d_in[11];
    const float* lm_w    = (const float*)d_in[12];

    float *p_x, *p_big;
    cudaGetSymbolAddress((void**)&p_x, g_x);
    cudaGetSymbolAddress((void**)&p_big, g_big);
    __half *pqkv, *pproj, *pfc1, *pfc2, *plm, *pan3, *pah3;
    cudaGetSymbolAddress((void**)&pqkv, w3_qkv);
    cudaGetSymbolAddress((void**)&pproj, w3_proj);
    cudaGetSymbolAddress((void**)&pfc1, w3_fc1);
    cudaGetSymbolAddress((void**)&pfc2, w3_fc2);
    cudaGetSymbolAddress((void**)&plm, w2_lm);
    cudaGetSymbolAddress((void**)&pan3, an3);
    cudaGetSymbolAddress((void**)&pah3, ah3);

    cudaFuncSetAttribute(gemm_kernel,
                         cudaFuncAttributeMaxDynamicSharedMemorySize, SMEM_BYTES);
    cudaFuncSetAttribute(gemm64_kernel,
                         cudaFuncAttributeMaxDynamicSharedMemorySize, SMEM64_BYTES);
    cudaFuncSetAttribute(lmhead_kernel,
                         cudaFuncAttributeMaxDynamicSharedMemorySize, SMEM_BYTES);

    const long long NTV = (long long)SEQ * VOCAB;
    int store_logits = ((long long)out_size >= NTV) ? 1 : 0;

    split_all_kernel<<<8192, 256>>>((const float4*)qkv_w, (const float4*)proj_w,
                                    (const float4*)fc1_w, (const float4*)fc2_w,
                                    (const float4*)lm_w,
                                    pqkv, pproj, pfc1, pfc2, plm);
    embed_kernel<<<SEQ, 256>>>(idx, emb);

    for (int l = 0; l < LNUM; l++) {
        const float* l1 = ln1_w + (size_t)l * DMODEL;
        const float* qn = q_norm + (size_t)l * HDIM;
        const float* kn = k_norm + (size_t)l * HDIM;
        const float* l2 = ln2_w + (size_t)l * DMODEL;
        __half* qkw = pqkv + (size_t)l * 2304 * K3D;
        __half* pw  = pproj + (size_t)l * 768 * K3D;
        __half* f1  = pfc1 + (size_t)l * 3072 * K3D;
        __half* f2  = pfc2 + (size_t)l * 768 * K3F;

        rmsnorm_kernel<<<SEQ, 256>>>(p_x, l1);
        gemm_kernel<<<dim3(SEQ / 128, 2304 / 128), 256, SMEM_BYTES>>>(
            pan3, qkw, p_big, nullptr, nullptr, SEQ, 2304, K3D, 0);
        if (l == 0) zero_kernel<<<1, 256>>>();
        {
            dim3 g(SEQ, NHEAD);
            rope_kernel<<<g, HDIM>>>(p_big, qn, kn);
        }
        {
            dim3 g(SEQ / 8, NHEAD);
            attn_kernel<<<g, 256>>>();
        }
        gemm64_kernel<<<dim3(SEQ / 64, DMODEL / 128), 256, SMEM64_BYTES>>>(
            pan3, pw, p_x, p_x, DMODEL, K3D);
        rmsnorm_kernel<<<SEQ, 256>>>(p_x, l2);
        gemm_kernel<<<dim3(SEQ / 128, FFDIM / 128), 256, SMEM_BYTES>>>(
            pan3, f1, nullptr, nullptr, pah3, SEQ, FFDIM, K3D, 2);
        gemm64_kernel<<<dim3(SEQ / 64, DMODEL / 128), 256, SMEM64_BYTES>>>(
            pah3, f2, p_x, p_x, DMODEL, K3F);
    }

    rmsnorm_kernel<<<SEQ, 256>>>(p_x, lnf_w);
    lmhead_kernel<<<dim3(SEQ / 128, VOCAB / 128), 256, SMEM_BYTES>>>(
        pan3, plm, (float*)d_out, targets, store_logits);
    if (store_logits) {
        float* lossp =
            ((long long)out_size > NTV) ? ((float*)d_out + NTV) : nullptr;
        loss_kernel<<<1, 256>>>(lossp);
    } else {
        loss_kernel<<<1, 256>>>((float*)d_out);
    }
}

// round 14
// speedup vs baseline: 1.1012x; 1.1012x over previous
#include <cuda_runtime.h>
#include <cuda_bf16.h>
#include <cuda_fp16.h>
#include <math.h>
#include <stdint.h>

// Model dims
#define LNUM 12
#define DMODEL 768
#define NHEAD 6
#define HDIM 128
#define FFDIM 3072
#define VOCAB 65536
#define SEQ 2048
#define EPSV 1e-5f
#define CAPV 30.0f

#define K3D (3 * DMODEL)    // 2304
#define K2D (2 * DMODEL)    // 1536 (lm_head 2-plane K)
#define K3F (3 * FFDIM)     // 9216

// GEMM tiling: 128x128 tile, BK=64, 3-stage cp.async, 2 CTAs/SM
#define LDS 72
#define SMEM_BYTES (3 * 128 * LDS * 2 * 2)   // 110592 B

// ---------------- scratch (static device arrays; no allocation) -------------
__device__ float g_x[SEQ * DMODEL];
__device__ float g_big[SEQ * K3D];
__device__ float g_q[SEQ * DMODEL];
__device__ float g_k[SEQ * DMODEL];
__device__ float g_v[SEQ * DMODEL];
__device__ float g_rowsum[SEQ];
__device__ float g_tl[SEQ];

// K-interleaved fp16 split planes: row n, cols [0,K)=hi,[K,2K)=lo,[2K,3K)=hi
__device__ __align__(16) __half w3_qkv[12LL * 2304 * K3D];
__device__ __align__(16) __half w3_proj[12LL * 768 * K3D];
__device__ __align__(16) __half w3_fc1[12LL * 3072 * K3D];
__device__ __align__(16) __half w3_fc2[12LL * 768 * K3F];
// lm_head: 2-plane [hi|lo], row stride K2D
__device__ __align__(16) __half w2_lm[65536LL * K2D];

// K-interleaved activation planes: row t, cols [0,K)=hi,[K,2K)=hi,[2K,3K)=lo
__device__ __align__(16) __half an3[SEQ * K3D];
__device__ __align__(16) __half ah3[SEQ * K3F];

// ---------------- helpers ----------------------------------------------------
__device__ __forceinline__ void split2h(float v, __half& h, __half& l) {
    h = __float2half_rn(v);
    l = __float2half_rn(v - __half2float(h));
}

__device__ __forceinline__ float blockReduceSum(float v) {
    __shared__ float sh[32];
    __syncthreads();
    int lane = threadIdx.x & 31, wid = threadIdx.x >> 5;
    #pragma unroll
    for (int o = 16; o; o >>= 1) v += __shfl_xor_sync(0xffffffffu, v, o);
    if (lane == 0) sh[wid] = v;
    __syncthreads();
    int nw = blockDim.x >> 5;
    v = (threadIdx.x < nw) ? sh[threadIdx.x] : 0.f;
    if (wid == 0) {
        #pragma unroll
        for (int o = 16; o; o >>= 1) v += __shfl_xor_sync(0xffffffffu, v, o);
        if (lane == 0) sh[0] = v;
    }
    __syncthreads();
    return sh[0];
}

__device__ __forceinline__ void ldsm4(uint32_t (&r)[4], uint32_t addr) {
    asm volatile("ldmatrix.sync.aligned.m8n8.x4.shared.b16 {%0,%1,%2,%3},[%4];"
                 : "=r"(r[0]), "=r"(r[1]), "=r"(r[2]), "=r"(r[3]) : "r"(addr));
}

__device__ __forceinline__ void mma_f32acc(float (&d)[4], const uint32_t (&a)[4],
                                           uint32_t b0, uint32_t b1) {
    asm volatile(
        "mma.sync.aligned.m16n8k16.row.col.f32.f16.f16.f32 "
        "{%0,%1,%2,%3},{%4,%5,%6,%7},{%8,%9},{%0,%1,%2,%3};"
        : "+f"(d[0]), "+f"(d[1]), "+f"(d[2]), "+f"(d[3])
        : "r"(a[0]), "r"(a[1]), "r"(a[2]), "r"(a[3]), "r"(b0), "r"(b1));
}

__device__ __forceinline__ void cp16(uint32_t dst, const void* src) {
    asm volatile("cp.async.cg.shared.global [%0], [%1], 16;" :: "r"(dst), "l"(src));
}
#define CP_COMMIT() asm volatile("cp.async.commit_group;")
#define CP_WAIT1() asm volatile("cp.async.wait_group 1;")

// load one 128x64 fp16 tile of A and B into a stage; separate row strides
__device__ __forceinline__ void load_stage(uint32_t sA, uint32_t sB,
                                           const __half* gA, const __half* gB,
                                           int ldA, int ldB, int tid) {
    int tRow = tid >> 3, tc = (tid & 7) * 8;
    #pragma unroll
    for (int p = 0; p < 4; p++) {
        int row = tRow + 32 * p;
        cp16(sA + (uint32_t)(row * LDS + tc) * 2, gA + (size_t)row * ldA + tc);
        cp16(sB + (uint32_t)(row * LDS + tc) * 2, gB + (size_t)row * ldB + tc);
    }
}

// ---------------- fused weight split: ONE launch -------------------------------
__device__ __forceinline__ void split_seg3(const float4* s, __half* d,
                                           unsigned n4, unsigned K,
                                           unsigned gid, unsigned gstride) {
    unsigned K4 = K >> 2;
    for (unsigned i = gid; i < n4; i += gstride) {
        float4 v = s[i];
        unsigned n = i / K4;
        unsigned k = (i - n * K4) << 2;
        __half* r = d + (size_t)n * 3 * K + k;
        float vv[4] = {v.x, v.y, v.z, v.w};
        #pragma unroll
        for (int j = 0; j < 4; j++) {
            __half h, l;
            split2h(vv[j], h, l);
            r[j] = h; r[K + j] = l; r[2 * K + j] = h;
        }
    }
}

__device__ __forceinline__ void split_seg2(const float4* s, __half* d,
                                           unsigned n4, unsigned K,
                                           unsigned gid, unsigned gstride) {
    unsigned K4 = K >> 2;
    for (unsigned i = gid; i < n4; i += gstride) {
        float4 v = s[i];
        unsigned n = i / K4;
        unsigned k = (i - n * K4) << 2;
        __half* r = d + (size_t)n * 2 * K + k;
        float vv[4] = {v.x, v.y, v.z, v.w};
        #pragma unroll
        for (int j = 0; j < 4; j++) {
            __half h, l;
            split2h(vv[j], h, l);
            r[j] = h; r[K + j] = l;
        }
    }
}

__global__ void split_all_kernel(const float4* qkv, const float4* proj,
                                 const float4* fc1, const float4* fc2,
                                 const float4* lm,
                                 __half* dqkv, __half* dproj,
                                 __half* dfc1, __half* dfc2, __half* dlm) {
    unsigned gid = blockIdx.x * blockDim.x + threadIdx.x;
    unsigned gs = gridDim.x * blockDim.x;
    split_seg3(qkv, dqkv, 12u * 2304 * 768 / 4, DMODEL, gid, gs);
    split_seg3(proj, dproj, 12u * 768 * 768 / 4, DMODEL, gid, gs);
    split_seg3(fc1, dfc1, 12u * 3072 * 768 / 4, DMODEL, gid, gs);
    split_seg3(fc2, dfc2, 12u * 768 * 3072 / 4, FFDIM, gid, gs);
    split_seg2(lm, dlm, 65536u * 768 / 4, DMODEL, gid, gs);
}

// ---------------- elementwise kernels ----------------------------------------
__global__ void embed_kernel(const int* __restrict__ idx,
                             const float* __restrict__ emb) {
    int t = blockIdx.x;
    int row = idx[t];
    const float* src = emb + (size_t)row * DMODEL;
    for (int i = threadIdx.x; i < DMODEL; i += blockDim.x)
        g_x[t * DMODEL + i] = src[i];
}

__global__ void rmsnorm_kernel(const float* __restrict__ x,
                               const float* __restrict__ w) {
    int t = blockIdx.x;
    const float* xr = x + (size_t)t * DMODEL;
    float s = 0.f;
    for (int i = threadIdx.x; i < DMODEL; i += blockDim.x) {
        float v = xr[i];
        s += v * v;
    }
    s = blockReduceSum(s);
    float r = rsqrtf(s / (float)DMODEL + EPSV);
    for (int i = threadIdx.x; i < DMODEL; i += blockDim.x) {
        float v = xr[i] * r * w[i];
        __half h, l;
        split2h(v, h, l);
        size_t o = (size_t)t * K3D + i;
        an3[o] = h; an3[o + DMODEL] = h; an3[o + 2 * DMODEL] = l;
    }
}

__global__ void rope_kernel(const float* __restrict__ qkv,
                            const float* __restrict__ qw,
                            const float* __restrict__ kw) {
    int t = blockIdx.x, h = blockIdx.y, d = threadIdx.x;
    const float* base = qkv + (size_t)t * K3D;
    float qd = base[h * HDIM + d];
    float kd = base[DMODEL + h * HDIM + d];
    float vd = base[2 * DMODEL + h * HDIM + d];
    float qs = blockReduceSum(qd * qd);
    float ks = blockReduceSum(kd * kd);
    float qn = qd * rsqrtf(qs / (float)HDIM + EPSV) * qw[d];
    float kn = kd * rsqrtf(ks / (float)HDIM + EPSV) * kw[d];
    __shared__ float sq[HDIM], sk[HDIM];
    sq[d] = qn; sk[d] = kn;
    __syncthreads();
    float expo = -(float)((d & 63) * 2) / (float)HDIM;
    float invf = expf(expo * logf(10000.f));
    float ang = (float)t * invf;
    float c = cosf(ang), s = sinf(ang);
    float qr = (d < 64) ? -sq[d + 64] : sq[d - 64];
    float kr = (d < 64) ? -sk[d + 64] : sk[d - 64];
    size_t oidx = (size_t)t * DMODEL + h * HDIM + d;
    g_q[oidx] = qn * c + qr * s;
    g_k[oidx] = kn * c + kr * s;
    g_v[oidx] = vd;
}

// ---------------- attention: tile-wise online softmax (lane = key) -----------
__global__ void __launch_bounds__(256) attn_kernel() {
    const int h = blockIdx.y;
    const int qbase = blockIdx.x * 8;
    const int tid = threadIdx.x;
    const int warp = tid >> 5, lane = tid & 31;
    const int qi = qbase + warp;
    __shared__ float4 Ktf[32][33];
    __shared__ float4 Vtf[32][33];
    __shared__ float4 sq4[8][32];

    {
        int r = tid >> 5, c4 = tid & 31;
        sq4[r][c4] = ((const float4*)(g_q + (size_t)(qbase + r) * DMODEL +
                                      h * HDIM))[c4];
    }

    float m = -1e30f, l = 0.f;
    float4 acc = make_float4(0.f, 0.f, 0.f, 0.f);
    const int ntiles = (qbase + 8 + 31) >> 5;

    for (int tb = 0; tb < ntiles; tb++) {
        int kb = tb << 5;
        __syncthreads();
        #pragma unroll
        for (int it = 0; it < 4; it++) {
            int i = tid + it * 256;
            int r = i >> 5, c4 = i & 31;
            Ktf[c4][r] = ((const float4*)(g_k + (size_t)(kb + r) * DMODEL +
                                          h * HDIM))[c4];
            Vtf[r][c4] = ((const float4*)(g_v + (size_t)(kb + r) * DMODEL +
                                          h * HDIM))[c4];
        }
        __syncthreads();

        int jmax = qi - kb + 1;
        if (jmax > 0) {
            float s0 = 0.f, s1 = 0.f, s2 = 0.f, s3 = 0.f;
            #pragma unroll
            for (int d4 = 0; d4 < 32; d4 += 4) {
                float4 q0 = sq4[warp][d4],     k0 = Ktf[d4][lane];
                float4 q1 = sq4[warp][d4 + 1], k1 = Ktf[d4 + 1][lane];
                float4 q2 = sq4[warp][d4 + 2], k2 = Ktf[d4 + 2][lane];
                float4 q3 = sq4[warp][d4 + 3], k3 = Ktf[d4 + 3][lane];
                s0 += q0.x * k0.x + q0.y * k0.y + q0.z * k0.z + q0.w * k0.w;
                s1 += q1.x * k1.x + q1.y * k1.y + q1.z * k1.z + q1.w * k1.w;
                s2 += q2.x * k2.x + q2.y * k2.y + q2.z * k2.z + q2.w * k2.w;
                s3 += q3.x * k3.x + q3.y * k3.y + q3.z * k3.z + q3.w * k3.w;
            }
            float sv = (s0 + s1 + s2 + s3) * 0.08838834764831845f;
            if (lane >= jmax) sv = -1e30f;
            float mt = sv;
            #pragma unroll
            for (int o = 16; o; o >>= 1)
                mt = fmaxf(mt, __shfl_xor_sync(0xffffffffu, mt, o));
            float mn = fmaxf(m, mt);
            float corr = __expf(m - mn);
            float p = __expf(sv - mn);
            float psum = p;
            #pragma unroll
            for (int o = 16; o; o >>= 1)
                psum += __shfl_xor_sync(0xffffffffu, psum, o);
            l = l * corr + psum;
            m = mn;
            acc.x *= corr; acc.y *= corr; acc.z *= corr; acc.w *= corr;
            #pragma unroll
            for (int j = 0; j < 32; j++) {
                float pj = __shfl_sync(0xffffffffu, p, j);
                float4 vv = Vtf[j][lane];
                acc.x += pj * vv.x; acc.y += pj * vv.y;
                acc.z += pj * vv.z; acc.w += pj * vv.w;
            }
        }
    }
    float inv = 1.f / l;
    float ov[4] = {acc.x * inv, acc.y * inv, acc.z * inv, acc.w * inv};
    #pragma unroll
    for (int q = 0; q < 4; q++) {
        int i = h * HDIM + lane * 4 + q;
        __half hh, ll;
        split2h(ov[q], hh, ll);
        size_t o = (size_t)qi * K3D + i;
        an3[o] = hh; an3[o + DMODEL] = hh; an3[o + 2 * DMODEL] = ll;
    }
}

// ---------------- pipelined fp16 GEMM 128x128: C = A * B^T --------------------
// epi: 0 = f32 store, 1 = +res f32 store, 2 = relu^2 -> triple fp16 O3,
//      3 = atomicAdd into C (split-K partial; blockIdx.z selects K chunk)
__global__ void __launch_bounds__(256, 2)
gemm_kernel(const __half* __restrict__ A, const __half* __restrict__ B,
            float* __restrict__ C, const float* __restrict__ res,
            __half* __restrict__ O3,
            int M, int N, int Kp, int epi, int ksplit) {
    extern __shared__ __half smem[];
    __half* sA = smem;
    __half* sB = smem + 3 * 128 * LDS;
    const int tid = threadIdx.x, lane = tid & 31, wid = tid >> 5;
    const int wm = wid >> 2, wn = wid & 3;
    const int m0 = blockIdx.x * 128, n0 = blockIdx.y * 128;
    const uint32_t sAu = (uint32_t)__cvta_generic_to_shared(sA);
    const uint32_t sBu = (uint32_t)__cvta_generic_to_shared(sB);
    const uint32_t stageB = 128 * LDS * 2;
    const int nk = Kp / 64 / ksplit;
    const int koff = blockIdx.z * nk * 64;
    const __half* gA = A + (size_t)m0 * Kp + koff;
    const __half* gB = B + (size_t)n0 * Kp + koff;

    float acc[4][4][4];
    #pragma unroll
    for (int a = 0; a < 4; a++)
        #pragma unroll
        for (int b = 0; b < 4; b++)
            #pragma unroll
            for (int c = 0; c < 4; c++) acc[a][b][c] = 0.f;

    load_stage(sAu, sBu, gA, gB, Kp, Kp, tid);
    CP_COMMIT();
    load_stage(sAu + stageB, sBu + stageB, gA + 64, gB + 64, Kp, Kp, tid);
    CP_COMMIT();

    for (int k = 0; k < nk; k++) {
        CP_WAIT1();
        __syncthreads();
        int st = k % 3;
        uint32_t aB = sAu + st * stageB;
        uint32_t bB = sBu + st * stageB;
        #pragma unroll
        for (int kh = 0; kh < 4; kh++) {
            uint32_t a[4][4], b[2][4];
            const int acol = kh * 16 + ((lane >> 4) << 3);
            #pragma unroll
            for (int mt = 0; mt < 4; mt++) {
                int arow = wm * 64 + mt * 16 + (lane & 15);
                ldsm4(a[mt], aB + (uint32_t)(arow * LDS + acol) * 2);
            }
            const int brow = wn * 32 + ((lane >> 4) << 3) + (lane & 7);
            const int bcol = kh * 16 + (((lane >> 3) & 1) << 3);
            #pragma unroll
            for (int p = 0; p < 2; p++)
                ldsm4(b[p], bB + (uint32_t)((brow + p * 16) * LDS + bcol) * 2);
            #pragma unroll
            for (int mt = 0; mt < 4; mt++)
                #pragma unroll
                for (int nt = 0; nt < 4; nt++)
                    mma_f32acc(acc[mt][nt], a[mt], b[nt >> 1][(nt & 1) * 2],
                               b[nt >> 1][(nt & 1) * 2 + 1]);
        }
        if (k + 2 < nk) {
            int s2 = (k + 2) % 3;
            load_stage(sAu + s2 * stageB, sBu + s2 * stageB,
                       gA + (size_t)(k + 2) * 64, gB + (size_t)(k + 2) * 64,
                       Kp, Kp, tid);
        }
        CP_COMMIT();
    }
    #pragma unroll
    for (int mt = 0; mt < 4; mt++)
        #pragma unroll
        for (int nt = 0; nt < 4; nt++)
            #pragma unroll
            for (int r = 0; r < 4; r++) {
                int row = m0 + wm * 64 + mt * 16 + (lane >> 2) + (r >> 1) * 8;
                int col = n0 + wn * 32 + nt * 8 + (lane & 3) * 2 + (r & 1);
                float vv = acc[mt][nt][r];
                size_t o = (size_t)row * N + col;
                if (epi == 0) {
                    C[o] = vv;
                } else if (epi == 1) {
                    C[o] = vv + res[o];
                } else if (epi == 3) {
                    atomicAdd(&C[o], vv);
                } else {
                    vv = fmaxf(vv, 0.f); vv = vv * vv;
                    __half h, l;
                    split2h(vv, h, l);
                    size_t o3 = (size_t)row * 3 * N + col;
                    O3[o3] = h; O3[o3 + N] = h; O3[o3 + 2 * N] = l;
                }
            }
}

// ---------------- lm_head: 2-plane GEMM (A stride K3D, Kp=K2D) ---------------
__global__ void __launch_bounds__(256, 2)
lmhead_kernel(const __half* __restrict__ A, const __half* __restrict__ B,
              float* __restrict__ out, const int* __restrict__ targets, int store) {
    const int N = VOCAB, Kp = K2D, ldA = K3D;
    extern __shared__ __half smem[];
    __half* sA = smem;
    __half* sB = smem + 3 * 128 * LDS;
    const int tid = threadIdx.x, lane = tid & 31, wid = tid >> 5;
    const int wm = wid >> 2, wn = wid & 3;
    const int m0 = blockIdx.x * 128, n0 = blockIdx.y * 128;
    const uint32_t sAu = (uint32_t)__cvta_generic_to_shared(sA);
    const uint32_t sBu = (uint32_t)__cvta_generic_to_shared(sB);
    const uint32_t stageB = 128 * LDS * 2;
    const __half* gA = A + (size_t)m0 * ldA;
    const __half* gB = B + (size_t)n0 * Kp;

    float acc[4][4][4];
    #pragma unroll
    for (int a = 0; a < 4; a++)
        #pragma unroll
        for (int b = 0; b < 4; b++)
            #pragma unroll
            for (int c = 0; c < 4; c++) acc[a][b][c] = 0.f;

    const int nk = Kp / 64;   // 24
    load_stage(sAu, sBu, gA, gB, ldA, Kp, tid);
    CP_COMMIT();
    load_stage(sAu + stageB, sBu + stageB, gA + 64, gB + 64, ldA, Kp, tid);
    CP_COMMIT();

    for (int k = 0; k < nk; k++) {
        CP_WAIT1();
        __syncthreads();
        int st = k % 3;
        uint32_t aB = sAu + st * stageB;
        uint32_t bB = sBu + st * stageB;
        #pragma unroll
        for (int kh = 0; kh < 4; kh++) {
            uint32_t a[4][4], b[2][4];
            const int acol = kh * 16 + ((lane >> 4) << 3);
            #pragma unroll
            for (int mt = 0; mt < 4; mt++) {
                int arow = wm * 64 + mt * 16 + (lane & 15);
                ldsm4(a[mt], aB + (uint32_t)(arow * LDS + acol) * 2);
            }
            const int brow = wn * 32 + ((lane >> 4) << 3) + (lane & 7);
            const int bcol = kh * 16 + (((lane >> 3) & 1) << 3);
            #pragma unroll
            for (int p = 0; p < 2; p++)
                ldsm4(b[p], bB + (uint32_t)((brow + p * 16) * LDS + bcol) * 2);
            #pragma unroll
            for (int mt = 0; mt < 4; mt++)
                #pragma unroll
                for (int nt = 0; nt < 4; nt++)
                    mma_f32acc(acc[mt][nt], a[mt], b[nt >> 1][(nt & 1) * 2],
                               b[nt >> 1][(nt & 1) * 2 + 1]);
        }
        if (k + 2 < nk) {
            int s2 = (k + 2) % 3;
            load_stage(sAu + s2 * stageB, sBu + s2 * stageB,
                       gA + (size_t)(k + 2) * 64, gB + (size_t)(k + 2) * 64,
                       ldA, Kp, tid);
        }
        CP_COMMIT();
    }
    float ps[8];
    #pragma unroll
    for (int i = 0; i < 8; i++) ps[i] = 0.f;
    #pragma unroll
    for (int mt = 0; mt < 4; mt++)
        #pragma unroll
        for (int nt = 0; nt < 4; nt++)
            #pragma unroll
            for (int r = 0; r < 4; r++) {
                int row = m0 + wm * 64 + mt * 16 + (lane >> 2) + (r >> 1) * 8;
                int col = n0 + wn * 32 + nt * 8 + (lane & 3) * 2 + (r & 1);
                float vv = CAPV * tanhf(acc[mt][nt][r] * (1.f / CAPV));
                if (store)
                    out[(size_t)row * N + col] =
                        __bfloat162float(__float2bfloat16(vv));
                ps[mt * 2 + (r >> 1)] += __expf(vv - CAPV);
                if (col == targets[row]) g_tl[row] = vv;
            }
    #pragma unroll
    for (int i = 0; i < 8; i++) {
        ps[i] += __shfl_xor_sync(0xffffffffu, ps[i], 1);
        ps[i] += __shfl_xor_sync(0xffffffffu, ps[i], 2);
    }
    __syncthreads();
    float* red = (float*)smem;
    if ((lane & 3) == 0) {
        #pragma unroll
        for (int mt = 0; mt < 4; mt++)
            #pragma unroll
            for (int hh = 0; hh < 2; hh++) {
                int rl = wm * 64 + mt * 16 + (lane >> 2) + hh * 8;
                red[rl * 4 + wn] = ps[mt * 2 + hh];
            }
    }
    __syncthreads();
    if (tid < 128) {
        float s = red[tid * 4] + red[tid * 4 + 1] + red[tid * 4 + 2] + red[tid * 4 + 3];
        atomicAdd(&g_rowsum[m0 + tid], s);
    }
}

__global__ void zero_kernel() {
    for (int i = threadIdx.x; i < SEQ; i += blockDim.x) g_rowsum[i] = 0.f;
}

__global__ void loss_kernel(float* out_f) {
    float s = 0.f;
    for (int t = threadIdx.x; t < SEQ; t += blockDim.x)
        s += CAPV + logf(g_rowsum[t]) - g_tl[t];
    s = blockReduceSum(s);
    if (threadIdx.x == 0 && out_f) out_f[0] = s / (float)SEQ;
}

// ---------------- launch ------------------------------------------------------
extern "C" void kernel_launch(void* const* d_in, const int* in_sizes, int n_in,
                              void* d_out, int out_size) {
    const int*   idx     = (const int*)d_in[0];
    const int*   targets = (const int*)d_in[1];
    const float* emb     = (const float*)d_in[2];
    const float* ln1_w   = (const float*)d_in[3];
    const float* qkv_w   = (const float*)d_in[4];
    const float* q_norm  = (const float*)d_in[5];
    const float* k_norm  = (const float*)d_in[6];
    const float* proj_w  = (const float*)d_in[7];
    const float* ln2_w   = (const float*)d_in[8];
    const float* fc1_w   = (const float*)d_in[9];
    const float* fc2_w   = (const float*)d_in[10];
    const float* lnf_w   = (const float*)d_in[11];
    const float* lm_w    = (const float*)d_in[12];

    float *p_x, *p_big;
    cudaGetSymbolAddress((void**)&p_x, g_x);
    cudaGetSymbolAddress((void**)&p_big, g_big);
    __half *pqkv, *pproj, *pfc1, *pfc2, *plm, *pan3, *pah3;
    cudaGetSymbolAddress((void**)&pqkv, w3_qkv);
    cudaGetSymbolAddress((void**)&pproj, w3_proj);
    cudaGetSymbolAddress((void**)&pfc1, w3_fc1);
    cudaGetSymbolAddress((void**)&pfc2, w3_fc2);
    cudaGetSymbolAddress((void**)&plm, w2_lm);
    cudaGetSymbolAddress((void**)&pan3, an3);
    cudaGetSymbolAddress((void**)&pah3, ah3);

    cudaFuncSetAttribute(gemm_kernel,
                         cudaFuncAttributeMaxDynamicSharedMemorySize, SMEM_BYTES);
    cudaFuncSetAttribute(lmhead_kernel,
                         cudaFuncAttributeMaxDynamicSharedMemorySize, SMEM_BYTES);

    const long long NTV = (long long)SEQ * VOCAB;
    int store_logits = ((long long)out_size >= NTV) ? 1 : 0;

    split_all_kernel<<<8192, 256>>>((const float4*)qkv_w, (const float4*)proj_w,
                                    (const float4*)fc1_w, (const float4*)fc2_w,
                                    (const float4*)lm_w,
                                    pqkv, pproj, pfc1, pfc2, plm);
    embed_kernel<<<SEQ, 256>>>(idx, emb);

    for (int l = 0; l < LNUM; l++) {
        const float* l1 = ln1_w + (size_t)l * DMODEL;
        const float* qn = q_norm + (size_t)l * HDIM;
        const float* kn = k_norm + (size_t)l * HDIM;
        const float* l2 = ln2_w + (size_t)l * DMODEL;
        __half* qkw = pqkv + (size_t)l * 2304 * K3D;
        __half* pw  = pproj + (size_t)l * 768 * K3D;
        __half* f1  = pfc1 + (size_t)l * 3072 * K3D;
        __half* f2  = pfc2 + (size_t)l * 768 * K3F;

        rmsnorm_kernel<<<SEQ, 256>>>(p_x, l1);
        gemm_kernel<<<dim3(SEQ / 128, 2304 / 128, 1), 256, SMEM_BYTES>>>(
            pan3, qkw, p_big, nullptr, nullptr, SEQ, 2304, K3D, 0, 1);
        if (l == 0) zero_kernel<<<1, 256>>>();
        {
            dim3 g(SEQ, NHEAD);
            rope_kernel<<<g, HDIM>>>(p_big, qn, kn);
        }
        {
            dim3 g(SEQ / 8, NHEAD);
            attn_kernel<<<g, 256>>>();
        }
        // proj: split-K=2, full 128x128 tiles, atomicAdd into residual x
        gemm_kernel<<<dim3(SEQ / 128, DMODEL / 128, 2), 256, SMEM_BYTES>>>(
            pan3, pw, p_x, nullptr, nullptr, SEQ, DMODEL, K3D, 3, 2);
        rmsnorm_kernel<<<SEQ, 256>>>(p_x, l2);
        gemm_kernel<<<dim3(SEQ / 128, FFDIM / 128, 1), 256, SMEM_BYTES>>>(
            pan3, f1, nullptr, nullptr, pah3, SEQ, FFDIM, K3D, 2, 1);
        // fc2: split-K=2, atomicAdd into residual x
        gemm_kernel<<<dim3(SEQ / 128, DMODEL / 128, 2), 256, SMEM_BYTES>>>(
            pah3, f2, p_x, nullptr, nullptr, SEQ, DMODEL, K3F, 3, 2);
    }

    rmsnorm_kernel<<<SEQ, 256>>>(p_x, lnf_w);
    lmhead_kernel<<<dim3(SEQ / 128, VOCAB / 128), 256, SMEM_BYTES>>>(
        pan3, plm, (float*)d_out, targets, store_logits);
    if (store_logits) {
        float* lossp =
            ((long long)out_size > NTV) ? ((float*)d_out + NTV) : nullptr;
        loss_kernel<<<1, 256>>>(lossp);
    } else {
        loss_kernel<<<1, 256>>>((float*)d_out);
    }
}

// round 15
// speedup vs baseline: 1.4335x; 1.3017x over previous
#include <cuda_runtime.h>
#include <cuda_bf16.h>
#include <cuda_fp16.h>
#include <math.h>
#include <stdint.h>

// Model dims
#define LNUM 12
#define DMODEL 768
#define NHEAD 6
#define HDIM 128
#define FFDIM 3072
#define VOCAB 65536
#define SEQ 2048
#define EPSV 1e-5f
#define CAPV 30.0f

#define K3D (3 * DMODEL)    // 2304
#define K2D (2 * DMODEL)    // 1536 (lm_head 2-plane K)
#define K3F (3 * FFDIM)     // 9216

// GEMM tiling: 128x128 tile, BK=64, 3-stage cp.async, 2 CTAs/SM
#define LDS 72
#define SMEM_BYTES (3 * 128 * LDS * 2 * 2)   // 110592 B
// attention dynamic smem: Ktf[32][35] + Vtf[32][32] + sq4[32][32] (float4)
#define ATTN_SMEM ((32 * 35 + 32 * 32 + 32 * 32) * 16)   // 50688 B

// ---------------- scratch (static device arrays; no allocation) -------------
__device__ float g_x[SEQ * DMODEL];
__device__ float g_big[SEQ * K3D];
__device__ float g_q[SEQ * DMODEL];
__device__ float g_k[SEQ * DMODEL];
__device__ float g_v[SEQ * DMODEL];
__device__ float g_rowsum[SEQ];
__device__ float g_tl[SEQ];

// K-interleaved fp16 split planes: row n, cols [0,K)=hi,[K,2K)=lo,[2K,3K)=hi
__device__ __align__(16) __half w3_qkv[12LL * 2304 * K3D];
__device__ __align__(16) __half w3_proj[12LL * 768 * K3D];
__device__ __align__(16) __half w3_fc1[12LL * 3072 * K3D];
__device__ __align__(16) __half w3_fc2[12LL * 768 * K3F];
// lm_head: 2-plane [hi|lo], row stride K2D
__device__ __align__(16) __half w2_lm[65536LL * K2D];

// K-interleaved activation planes: row t, cols [0,K)=hi,[K,2K)=hi,[2K,3K)=lo
__device__ __align__(16) __half an3[SEQ * K3D];
__device__ __align__(16) __half ah3[SEQ * K3F];

// ---------------- helpers ----------------------------------------------------
__device__ __forceinline__ void split2h(float v, __half& h, __half& l) {
    h = __float2half_rn(v);
    l = __float2half_rn(v - __half2float(h));
}

__device__ __forceinline__ float blockReduceSum(float v) {
    __shared__ float sh[32];
    __syncthreads();
    int lane = threadIdx.x & 31, wid = threadIdx.x >> 5;
    #pragma unroll
    for (int o = 16; o; o >>= 1) v += __shfl_xor_sync(0xffffffffu, v, o);
    if (lane == 0) sh[wid] = v;
    __syncthreads();
    int nw = blockDim.x >> 5;
    v = (threadIdx.x < nw) ? sh[threadIdx.x] : 0.f;
    if (wid == 0) {
        #pragma unroll
        for (int o = 16; o; o >>= 1) v += __shfl_xor_sync(0xffffffffu, v, o);
        if (lane == 0) sh[0] = v;
    }
    __syncthreads();
    return sh[0];
}

__device__ __forceinline__ void ldsm4(uint32_t (&r)[4], uint32_t addr) {
    asm volatile("ldmatrix.sync.aligned.m8n8.x4.shared.b16 {%0,%1,%2,%3},[%4];"
                 : "=r"(r[0]), "=r"(r[1]), "=r"(r[2]), "=r"(r[3]) : "r"(addr));
}

__device__ __forceinline__ void mma_f32acc(float (&d)[4], const uint32_t (&a)[4],
                                           uint32_t b0, uint32_t b1) {
    asm volatile(
        "mma.sync.aligned.m16n8k16.row.col.f32.f16.f16.f32 "
        "{%0,%1,%2,%3},{%4,%5,%6,%7},{%8,%9},{%0,%1,%2,%3};"
        : "+f"(d[0]), "+f"(d[1]), "+f"(d[2]), "+f"(d[3])
        : "r"(a[0]), "r"(a[1]), "r"(a[2]), "r"(a[3]), "r"(b0), "r"(b1));
}

__device__ __forceinline__ void cp16(uint32_t dst, const void* src) {
    asm volatile("cp.async.cg.shared.global [%0], [%1], 16;" :: "r"(dst), "l"(src));
}
#define CP_COMMIT() asm volatile("cp.async.commit_group;")
#define CP_WAIT1() asm volatile("cp.async.wait_group 1;")

// load one 128x64 fp16 tile of A and B into a stage; separate row strides
__device__ __forceinline__ void load_stage(uint32_t sA, uint32_t sB,
                                           const __half* gA, const __half* gB,
                                           int ldA, int ldB, int tid) {
    int tRow = tid >> 3, tc = (tid & 7) * 8;
    #pragma unroll
    for (int p = 0; p < 4; p++) {
        int row = tRow + 32 * p;
        cp16(sA + (uint32_t)(row * LDS + tc) * 2, gA + (size_t)row * ldA + tc);
        cp16(sB + (uint32_t)(row * LDS + tc) * 2, gB + (size_t)row * ldB + tc);
    }
}

// ---------------- fused weight split: ONE launch -------------------------------
__device__ __forceinline__ void split_seg3(const float4* s, __half* d,
                                           unsigned n4, unsigned K,
                                           unsigned gid, unsigned gstride) {
    unsigned K4 = K >> 2;
    for (unsigned i = gid; i < n4; i += gstride) {
        float4 v = s[i];
        unsigned n = i / K4;
        unsigned k = (i - n * K4) << 2;
        __half* r = d + (size_t)n * 3 * K + k;
        float vv[4] = {v.x, v.y, v.z, v.w};
        #pragma unroll
        for (int j = 0; j < 4; j++) {
            __half h, l;
            split2h(vv[j], h, l);
            r[j] = h; r[K + j] = l; r[2 * K + j] = h;
        }
    }
}

__device__ __forceinline__ void split_seg2(const float4* s, __half* d,
                                           unsigned n4, unsigned K,
                                           unsigned gid, unsigned gstride) {
    unsigned K4 = K >> 2;
    for (unsigned i = gid; i < n4; i += gstride) {
        float4 v = s[i];
        unsigned n = i / K4;
        unsigned k = (i - n * K4) << 2;
        __half* r = d + (size_t)n * 2 * K + k;
        float vv[4] = {v.x, v.y, v.z, v.w};
        #pragma unroll
        for (int j = 0; j < 4; j++) {
            __half h, l;
            split2h(vv[j], h, l);
            r[j] = h; r[K + j] = l;
        }
    }
}

__global__ void split_all_kernel(const float4* qkv, const float4* proj,
                                 const float4* fc1, const float4* fc2,
                                 const float4* lm,
                                 __half* dqkv, __half* dproj,
                                 __half* dfc1, __half* dfc2, __half* dlm) {
    unsigned gid = blockIdx.x * blockDim.x + threadIdx.x;
    unsigned gs = gridDim.x * blockDim.x;
    split_seg3(qkv, dqkv, 12u * 2304 * 768 / 4, DMODEL, gid, gs);
    split_seg3(proj, dproj, 12u * 768 * 768 / 4, DMODEL, gid, gs);
    split_seg3(fc1, dfc1, 12u * 3072 * 768 / 4, DMODEL, gid, gs);
    split_seg3(fc2, dfc2, 12u * 768 * 3072 / 4, FFDIM, gid, gs);
    split_seg2(lm, dlm, 65536u * 768 / 4, DMODEL, gid, gs);
}

// ---------------- elementwise kernels ----------------------------------------
__global__ void embed_kernel(const int* __restrict__ idx,
                             const float* __restrict__ emb) {
    int t = blockIdx.x;
    int row = idx[t];
    const float* src = emb + (size_t)row * DMODEL;
    for (int i = threadIdx.x; i < DMODEL; i += blockDim.x)
        g_x[t * DMODEL + i] = src[i];
}

__global__ void rmsnorm_kernel(const float* __restrict__ x,
                               const float* __restrict__ w) {
    int t = blockIdx.x;
    const float* xr = x + (size_t)t * DMODEL;
    float s = 0.f;
    for (int i = threadIdx.x; i < DMODEL; i += blockDim.x) {
        float v = xr[i];
        s += v * v;
    }
    s = blockReduceSum(s);
    float r = rsqrtf(s / (float)DMODEL + EPSV);
    for (int i = threadIdx.x; i < DMODEL; i += blockDim.x) {
        float v = xr[i] * r * w[i];
        __half h, l;
        split2h(v, h, l);
        size_t o = (size_t)t * K3D + i;
        an3[o] = h; an3[o + DMODEL] = h; an3[o + 2 * DMODEL] = l;
    }
}

__global__ void rope_kernel(const float* __restrict__ qkv,
                            const float* __restrict__ qw,
                            const float* __restrict__ kw) {
    int t = blockIdx.x, h = blockIdx.y, d = threadIdx.x;
    const float* base = qkv + (size_t)t * K3D;
    float qd = base[h * HDIM + d];
    float kd = base[DMODEL + h * HDIM + d];
    float vd = base[2 * DMODEL + h * HDIM + d];
    float qs = blockReduceSum(qd * qd);
    float ks = blockReduceSum(kd * kd);
    float qn = qd * rsqrtf(qs / (float)HDIM + EPSV) * qw[d];
    float kn = kd * rsqrtf(ks / (float)HDIM + EPSV) * kw[d];
    __shared__ float sq[HDIM], sk[HDIM];
    sq[d] = qn; sk[d] = kn;
    __syncthreads();
    float expo = -(float)((d & 63) * 2) / (float)HDIM;
    float invf = expf(expo * logf(10000.f));
    float ang = (float)t * invf;
    float c = cosf(ang), s = sinf(ang);
    float qr = (d < 64) ? -sq[d + 64] : sq[d - 64];
    float kr = (d < 64) ? -sk[d + 64] : sk[d - 64];
    size_t oidx = (size_t)t * DMODEL + h * HDIM + d;
    g_q[oidx] = qn * c + qr * s;
    g_k[oidx] = kn * c + kr * s;
    g_v[oidx] = vd;
}

// ---------------- attention: 4 queries per warp, tile-wise online softmax ----
// Block = 8 warps x 4 queries = 32 queries. Lane = key within 32-key tile.
// K/V smem reads amortized over 4 queries (crossbar was the bottleneck).
__global__ void __launch_bounds__(256) attn_kernel() {
    extern __shared__ float4 dyn[];
    float4 (*Ktf)[35] = (float4(*)[35])dyn;                      // [d4][key]
    float4 (*Vtf)[32] = (float4(*)[32])(dyn + 32 * 35);          // [key][d4]
    float4 (*sq4)[32] = (float4(*)[32])(dyn + 32 * 35 + 32 * 32);// [q][d4]
    const int h = blockIdx.y;
    const int qbase = blockIdx.x * 32;
    const int tid = threadIdx.x;
    const int warp = tid >> 5, lane = tid & 31;
    const int q0i = qbase + warp * 4;

    // load 32 queries x 128 dims
    #pragma unroll
    for (int it = 0; it < 4; it++) {
        int i = tid + it * 256;
        int r = i >> 5, c4 = i & 31;
        sq4[r][c4] = ((const float4*)(g_q + (size_t)(qbase + r) * DMODEL +
                                      h * HDIM))[c4];
    }

    float m[4], l[4];
    float4 acc[4];
    #pragma unroll
    for (int qq = 0; qq < 4; qq++) {
        m[qq] = -1e30f; l[qq] = 0.f;
        acc[qq] = make_float4(0.f, 0.f, 0.f, 0.f);
    }
    const int ntiles = (qbase >> 5) + 1;

    for (int tb = 0; tb < ntiles; tb++) {
        int kb = tb << 5;
        __syncthreads();
        #pragma unroll
        for (int it = 0; it < 4; it++) {
            int i = tid + it * 256;
            int r = i >> 5, c4 = i & 31;
            Ktf[c4][r] = ((const float4*)(g_k + (size_t)(kb + r) * DMODEL +
                                          h * HDIM))[c4];
            Vtf[r][c4] = ((const float4*)(g_v + (size_t)(kb + r) * DMODEL +
                                          h * HDIM))[c4];
        }
        __syncthreads();

        // scores for 4 queries; lane = key
        float s[4] = {0.f, 0.f, 0.f, 0.f};
        #pragma unroll
        for (int d4 = 0; d4 < 32; d4 += 4) {
            float4 k0 = Ktf[d4][lane],     k1 = Ktf[d4 + 1][lane];
            float4 k2 = Ktf[d4 + 2][lane], k3 = Ktf[d4 + 3][lane];
            #pragma unroll
            for (int qq = 0; qq < 4; qq++) {
                float4 q0 = sq4[warp * 4 + qq][d4];
                float4 q1 = sq4[warp * 4 + qq][d4 + 1];
                float4 q2 = sq4[warp * 4 + qq][d4 + 2];
                float4 q3 = sq4[warp * 4 + qq][d4 + 3];
                s[qq] += q0.x * k0.x + q0.y * k0.y + q0.z * k0.z + q0.w * k0.w
                       + q1.x * k1.x + q1.y * k1.y + q1.z * k1.z + q1.w * k1.w
                       + q2.x * k2.x + q2.y * k2.y + q2.z * k2.z + q2.w * k2.w
                       + q3.x * k3.x + q3.y * k3.y + q3.z * k3.z + q3.w * k3.w;
            }
        }
        // online softmax update per query
        float p4[4];
        #pragma unroll
        for (int qq = 0; qq < 4; qq++) {
            int jmax = q0i + qq - kb + 1;        // >= 1 always (kb <= qbase)
            float sv = s[qq] * 0.08838834764831845f;
            if (lane >= jmax) sv = -1e30f;
            float mt = sv;
            #pragma unroll
            for (int o = 16; o; o >>= 1)
                mt = fmaxf(mt, __shfl_xor_sync(0xffffffffu, mt, o));
            float mn = fmaxf(m[qq], mt);
            float corr = __expf(m[qq] - mn);
            float p = __expf(sv - mn);
            float psum = p;
            #pragma unroll
            for (int o = 16; o; o >>= 1)
                psum += __shfl_xor_sync(0xffffffffu, psum, o);
            l[qq] = l[qq] * corr + psum;
            m[qq] = mn;
            acc[qq].x *= corr; acc[qq].y *= corr;
            acc[qq].z *= corr; acc[qq].w *= corr;
            p4[qq] = p;
        }
        // PV: V vector loaded once, used for 4 queries
        #pragma unroll
        for (int j = 0; j < 32; j++) {
            float4 vv = Vtf[j][lane];
            #pragma unroll
            for (int qq = 0; qq < 4; qq++) {
                float pj = __shfl_sync(0xffffffffu, p4[qq], j);
                acc[qq].x += pj * vv.x; acc[qq].y += pj * vv.y;
                acc[qq].z += pj * vv.z; acc[qq].w += pj * vv.w;
            }
        }
    }
    #pragma unroll
    for (int qq = 0; qq < 4; qq++) {
        float inv = 1.f / l[qq];
        float ov[4] = {acc[qq].x * inv, acc[qq].y * inv,
                       acc[qq].z * inv, acc[qq].w * inv};
        #pragma unroll
        for (int q = 0; q < 4; q++) {
            int i = h * HDIM + lane * 4 + q;
            __half hh, ll;
            split2h(ov[q], hh, ll);
            size_t o = (size_t)(q0i + qq) * K3D + i;
            an3[o] = hh; an3[o + DMODEL] = hh; an3[o + 2 * DMODEL] = ll;
        }
    }
}

// ---------------- pipelined fp16 GEMM 128x128: C = A * B^T --------------------
// epi: 0 = f32 store, 1 = +res f32 store, 2 = relu^2 -> triple fp16 O3,
//      3 = atomicAdd into C (split-K partial; blockIdx.z selects K chunk)
__global__ void __launch_bounds__(256, 2)
gemm_kernel(const __half* __restrict__ A, const __half* __restrict__ B,
            float* __restrict__ C, const float* __restrict__ res,
            __half* __restrict__ O3,
            int M, int N, int Kp, int epi, int ksplit) {
    extern __shared__ __half smem[];
    __half* sA = smem;
    __half* sB = smem + 3 * 128 * LDS;
    const int tid = threadIdx.x, lane = tid & 31, wid = tid >> 5;
    const int wm = wid >> 2, wn = wid & 3;
    const int m0 = blockIdx.x * 128, n0 = blockIdx.y * 128;
    const uint32_t sAu = (uint32_t)__cvta_generic_to_shared(sA);
    const uint32_t sBu = (uint32_t)__cvta_generic_to_shared(sB);
    const uint32_t stageB = 128 * LDS * 2;
    const int nk = Kp / 64 / ksplit;
    const int koff = blockIdx.z * nk * 64;
    const __half* gA = A + (size_t)m0 * Kp + koff;
    const __half* gB = B + (size_t)n0 * Kp + koff;

    float acc[4][4][4];
    #pragma unroll
    for (int a = 0; a < 4; a++)
        #pragma unroll
        for (int b = 0; b < 4; b++)
            #pragma unroll
            for (int c = 0; c < 4; c++) acc[a][b][c] = 0.f;

    load_stage(sAu, sBu, gA, gB, Kp, Kp, tid);
    CP_COMMIT();
    load_stage(sAu + stageB, sBu + stageB, gA + 64, gB + 64, Kp, Kp, tid);
    CP_COMMIT();

    for (int k = 0; k < nk; k++) {
        CP_WAIT1();
        __syncthreads();
        int st = k % 3;
        uint32_t aB = sAu + st * stageB;
        uint32_t bB = sBu + st * stageB;
        #pragma unroll
        for (int kh = 0; kh < 4; kh++) {
            uint32_t a[4][4], b[2][4];
            const int acol = kh * 16 + ((lane >> 4) << 3);
            #pragma unroll
            for (int mt = 0; mt < 4; mt++) {
                int arow = wm * 64 + mt * 16 + (lane & 15);
                ldsm4(a[mt], aB + (uint32_t)(arow * LDS + acol) * 2);
            }
            const int brow = wn * 32 + ((lane >> 4) << 3) + (lane & 7);
            const int bcol = kh * 16 + (((lane >> 3) & 1) << 3);
            #pragma unroll
            for (int p = 0; p < 2; p++)
                ldsm4(b[p], bB + (uint32_t)((brow + p * 16) * LDS + bcol) * 2);
            #pragma unroll
            for (int mt = 0; mt < 4; mt++)
                #pragma unroll
                for (int nt = 0; nt < 4; nt++)
                    mma_f32acc(acc[mt][nt], a[mt], b[nt >> 1][(nt & 1) * 2],
                               b[nt >> 1][(nt & 1) * 2 + 1]);
        }
        if (k + 2 < nk) {
            int s2 = (k + 2) % 3;
            load_stage(sAu + s2 * stageB, sBu + s2 * stageB,
                       gA + (size_t)(k + 2) * 64, gB + (size_t)(k + 2) * 64,
                       Kp, Kp, tid);
        }
        CP_COMMIT();
    }
    #pragma unroll
    for (int mt = 0; mt < 4; mt++)
        #pragma unroll
        for (int nt = 0; nt < 4; nt++)
            #pragma unroll
            for (int r = 0; r < 4; r++) {
                int row = m0 + wm * 64 + mt * 16 + (lane >> 2) + (r >> 1) * 8;
                int col = n0 + wn * 32 + nt * 8 + (lane & 3) * 2 + (r & 1);
                float vv = acc[mt][nt][r];
                size_t o = (size_t)row * N + col;
                if (epi == 0) {
                    C[o] = vv;
                } else if (epi == 1) {
                    C[o] = vv + res[o];
                } else if (epi == 3) {
                    atomicAdd(&C[o], vv);
                } else {
                    vv = fmaxf(vv, 0.f); vv = vv * vv;
                    __half h, l;
                    split2h(vv, h, l);
                    size_t o3 = (size_t)row * 3 * N + col;
                    O3[o3] = h; O3[o3 + N] = h; O3[o3 + 2 * N] = l;
                }
            }
}

// ---------------- lm_head: 2-plane GEMM (A stride K3D, Kp=K2D) ---------------
__global__ void __launch_bounds__(256, 2)
lmhead_kernel(const __half* __restrict__ A, const __half* __restrict__ B,
              float* __restrict__ out, const int* __restrict__ targets, int store) {
    const int N = VOCAB, Kp = K2D, ldA = K3D;
    extern __shared__ __half smem[];
    __half* sA = smem;
    __half* sB = smem + 3 * 128 * LDS;
    const int tid = threadIdx.x, lane = tid & 31, wid = tid >> 5;
    const int wm = wid >> 2, wn = wid & 3;
    const int m0 = blockIdx.x * 128, n0 = blockIdx.y * 128;
    const uint32_t sAu = (uint32_t)__cvta_generic_to_shared(sA);
    const uint32_t sBu = (uint32_t)__cvta_generic_to_shared(sB);
    const uint32_t stageB = 128 * LDS * 2;
    const __half* gA = A + (size_t)m0 * ldA;
    const __half* gB = B + (size_t)n0 * Kp;

    float acc[4][4][4];
    #pragma unroll
    for (int a = 0; a < 4; a++)
        #pragma unroll
        for (int b = 0; b < 4; b++)
            #pragma unroll
            for (int c = 0; c < 4; c++) acc[a][b][c] = 0.f;

    const int nk = Kp / 64;   // 24
    load_stage(sAu, sBu, gA, gB, ldA, Kp, tid);
    CP_COMMIT();
    load_stage(sAu + stageB, sBu + stageB, gA + 64, gB + 64, ldA, Kp, tid);
    CP_COMMIT();

    for (int k = 0; k < nk; k++) {
        CP_WAIT1();
        __syncthreads();
        int st = k % 3;
        uint32_t aB = sAu + st * stageB;
        uint32_t bB = sBu + st * stageB;
        #pragma unroll
        for (int kh = 0; kh < 4; kh++) {
            uint32_t a[4][4], b[2][4];
            const int acol = kh * 16 + ((lane >> 4) << 3);
            #pragma unroll
            for (int mt = 0; mt < 4; mt++) {
                int arow = wm * 64 + mt * 16 + (lane & 15);
                ldsm4(a[mt], aB + (uint32_t)(arow * LDS + acol) * 2);
            }
            const int brow = wn * 32 + ((lane >> 4) << 3) + (lane & 7);
            const int bcol = kh * 16 + (((lane >> 3) & 1) << 3);
            #pragma unroll
            for (int p = 0; p < 2; p++)
                ldsm4(b[p], bB + (uint32_t)((brow + p * 16) * LDS + bcol) * 2);
            #pragma unroll
            for (int mt = 0; mt < 4; mt++)
                #pragma unroll
                for (int nt = 0; nt < 4; nt++)
                    mma_f32acc(acc[mt][nt], a[mt], b[nt >> 1][(nt & 1) * 2],
                               b[nt >> 1][(nt & 1) * 2 + 1]);
        }
        if (k + 2 < nk) {
            int s2 = (k + 2) % 3;
            load_stage(sAu + s2 * stageB, sBu + s2 * stageB,
                       gA + (size_t)(k + 2) * 64, gB + (size_t)(k + 2) * 64,
                       ldA, Kp, tid);
        }
        CP_COMMIT();
    }
    float ps[8];
    #pragma unroll
    for (int i = 0; i < 8; i++) ps[i] = 0.f;
    #pragma unroll
    for (int mt = 0; mt < 4; mt++)
        #pragma unroll
        for (int nt = 0; nt < 4; nt++)
            #pragma unroll
            for (int r = 0; r < 4; r++) {
                int row = m0 + wm * 64 + mt * 16 + (lane >> 2) + (r >> 1) * 8;
                int col = n0 + wn * 32 + nt * 8 + (lane & 3) * 2 + (r & 1);
                float vv = CAPV * tanhf(acc[mt][nt][r] * (1.f / CAPV));
                if (store)
                    out[(size_t)row * N + col] =
                        __bfloat162float(__float2bfloat16(vv));
                ps[mt * 2 + (r >> 1)] += __expf(vv - CAPV);
                if (col == targets[row]) g_tl[row] = vv;
            }
    #pragma unroll
    for (int i = 0; i < 8; i++) {
        ps[i] += __shfl_xor_sync(0xffffffffu, ps[i], 1);
        ps[i] += __shfl_xor_sync(0xffffffffu, ps[i], 2);
    }
    __syncthreads();
    float* red = (float*)smem;
    if ((lane & 3) == 0) {
        #pragma unroll
        for (int mt = 0; mt < 4; mt++)
            #pragma unroll
            for (int hh = 0; hh < 2; hh++) {
                int rl = wm * 64 + mt * 16 + (lane >> 2) + hh * 8;
                red[rl * 4 + wn] = ps[mt * 2 + hh];
            }
    }
    __syncthreads();
    if (tid < 128) {
        float s = red[tid * 4] + red[tid * 4 + 1] + red[tid * 4 + 2] + red[tid * 4 + 3];
        atomicAdd(&g_rowsum[m0 + tid], s);
    }
}

__global__ void zero_kernel() {
    for (int i = threadIdx.x; i < SEQ; i += blockDim.x) g_rowsum[i] = 0.f;
}

__global__ void loss_kernel(float* out_f) {
    float s = 0.f;
    for (int t = threadIdx.x; t < SEQ; t += blockDim.x)
        s += CAPV + logf(g_rowsum[t]) - g_tl[t];
    s = blockReduceSum(s);
    if (threadIdx.x == 0 && out_f) out_f[0] = s / (float)SEQ;
}

// ---------------- launch ------------------------------------------------------
extern "C" void kernel_launch(void* const* d_in, const int* in_sizes, int n_in,
                              void* d_out, int out_size) {
    const int*   idx     = (const int*)d_in[0];
    const int*   targets = (const int*)d_in[1];
    const float* emb     = (const float*)d_in[2];
    const float* ln1_w   = (const float*)d_in[3];
    const float* qkv_w   = (const float*)d_in[4];
    const float* q_norm  = (const float*)d_in[5];
    const float* k_norm  = (const float*)d_in[6];
    const float* proj_w  = (const float*)d_in[7];
    const float* ln2_w   = (const float*)d_in[8];
    const float* fc1_w   = (const float*)d_in[9];
    const float* fc2_w   = (const float*)d_in[10];
    const float* lnf_w   = (const float*)d_in[11];
    const float* lm_w    = (const float*)d_in[12];

    float *p_x, *p_big;
    cudaGetSymbolAddress((void**)&p_x, g_x);
    cudaGetSymbolAddress((void**)&p_big, g_big);
    __half *pqkv, *pproj, *pfc1, *pfc2, *plm, *pan3, *pah3;
    cudaGetSymbolAddress((void**)&pqkv, w3_qkv);
    cudaGetSymbolAddress((void**)&pproj, w3_proj);
    cudaGetSymbolAddress((void**)&pfc1, w3_fc1);
    cudaGetSymbolAddress((void**)&pfc2, w3_fc2);
    cudaGetSymbolAddress((void**)&plm, w2_lm);
    cudaGetSymbolAddress((void**)&pan3, an3);
    cudaGetSymbolAddress((void**)&pah3, ah3);

    cudaFuncSetAttribute(gemm_kernel,
                         cudaFuncAttributeMaxDynamicSharedMemorySize, SMEM_BYTES);
    cudaFuncSetAttribute(lmhead_kernel,
                         cudaFuncAttributeMaxDynamicSharedMemorySize, SMEM_BYTES);
    cudaFuncSetAttribute(attn_kernel,
                         cudaFuncAttributeMaxDynamicSharedMemorySize, ATTN_SMEM);

    const long long NTV = (long long)SEQ * VOCAB;
    int store_logits = ((long long)out_size >= NTV) ? 1 : 0;

    split_all_kernel<<<8192, 256>>>((const float4*)qkv_w, (const float4*)proj_w,
                                    (const float4*)fc1_w, (const float4*)fc2_w,
                                    (const float4*)lm_w,
                                    pqkv, pproj, pfc1, pfc2, plm);
    embed_kernel<<<SEQ, 256>>>(idx, emb);

    for (int l = 0; l < LNUM; l++) {
        const float* l1 = ln1_w + (size_t)l * DMODEL;
        const float* qn = q_norm + (size_t)l * HDIM;
        const float* kn = k_norm + (size_t)l * HDIM;
        const float* l2 = ln2_w + (size_t)l * DMODEL;
        __half* qkw = pqkv + (size_t)l * 2304 * K3D;
        __half* pw  = pproj + (size_t)l * 768 * K3D;
        __half* f1  = pfc1 + (size_t)l * 3072 * K3D;
        __half* f2  = pfc2 + (size_t)l * 768 * K3F;

        rmsnorm_kernel<<<SEQ, 256>>>(p_x, l1);
        gemm_kernel<<<dim3(SEQ / 128, 2304 / 128, 1), 256, SMEM_BYTES>>>(
            pan3, qkw, p_big, nullptr, nullptr, SEQ, 2304, K3D, 0, 1);
        if (l == 0) zero_kernel<<<1, 256>>>();
        {
            dim3 g(SEQ, NHEAD);
            rope_kernel<<<g, HDIM>>>(p_big, qn, kn);
        }
        {
            dim3 g(SEQ / 32, NHEAD);
            attn_kernel<<<g, 256, ATTN_SMEM>>>();
        }
        // proj: split-K=2, full 128x128 tiles, atomicAdd into residual x
        gemm_kernel<<<dim3(SEQ / 128, DMODEL / 128, 2), 256, SMEM_BYTES>>>(
            pan3, pw, p_x, nullptr, nullptr, SEQ, DMODEL, K3D, 3, 2);
        rmsnorm_kernel<<<SEQ, 256>>>(p_x, l2);
        gemm_kernel<<<dim3(SEQ / 128, FFDIM / 128, 1), 256, SMEM_BYTES>>>(
            pan3, f1, nullptr, nullptr, pah3, SEQ, FFDIM, K3D, 2, 1);
        // fc2: split-K=2, atomicAdd into residual x
        gemm_kernel<<<dim3(SEQ / 128, DMODEL / 128, 2), 256, SMEM_BYTES>>>(
            pah3, f2, p_x, nullptr, nullptr, SEQ, DMODEL, K3F, 3, 2);
    }

    rmsnorm_kernel<<<SEQ, 256>>>(p_x, lnf_w);
    lmhead_kernel<<<dim3(SEQ / 128, VOCAB / 128), 256, SMEM_BYTES>>>(
        pan3, plm, (float*)d_out, targets, store_logits);
    if (store_logits) {
        float* lossp =
            ((long long)out_size > NTV) ? ((float*)d_out + NTV) : nullptr;
        loss_kernel<<<1, 256>>>(lossp);
    } else {
        loss_kernel<<<1, 256>>>((float*)d_out);
    }
}